// round 7
// baseline (speedup 1.0000x reference)
#include <cuda_runtime.h>
#include <cuda_fp16.h>
#include <cstdint>
#include <cstddef>

#define BATCH   16384
#define HID     2048
#define NLAYER  8
#define PIN     25

#define MT      256
#define NT      128
#define KC      64                  // 64 fp16 k-values = 128B per row
#define NCH     (HID / KC)          // 32
#define ABYTES  (MT * 128)          // 32768
#define BBYTES  (NT * 128)          // 16384
#define STGB    (ABYTES + BBYTES)   // 49152
#define DYNSMEM (4 * STGB + 1024)   // 197632
#define NTHR    256

// ---------------- device scratch (allocation-free) ----------------
__device__ float  g_h0[(size_t)BATCH * HID];     // exact fp32 activations
__device__ float  g_h1[(size_t)BATCH * HID];
__device__ __half g_ta0[(size_t)BATCH * HID];    // fp16-rounded MMA copies
__device__ __half g_ta1[(size_t)BATCH * HID];
__device__ __half g_wt[(size_t)NLAYER * HID * HID];  // W^T fp16 [l][n][k]
__device__ float  g_patch[(size_t)BATCH * PIN];

// ---------------- helpers ----------------
__device__ __forceinline__ uint32_t smem_u32(const void* p) {
    uint32_t a;
    asm("{ .reg .u64 t; cvta.to.shared.u64 t, %1; cvt.u32.u64 %0, t; }" : "=r"(a) : "l"(p));
    return a;
}

__device__ __forceinline__ void cp_async16(uint32_t s, const void* g) {
    asm volatile("cp.async.cg.shared.global [%0], [%1], 16;" :: "r"(s), "l"(g) : "memory");
}

__device__ __forceinline__ void mma_f16(float* c, const uint32_t* a, const uint32_t* b) {
    asm volatile(
        "mma.sync.aligned.m16n8k16.row.col.f32.f16.f16.f32 "
        "{%0,%1,%2,%3}, {%4,%5,%6,%7}, {%8,%9}, {%0,%1,%2,%3};"
        : "+f"(c[0]), "+f"(c[1]), "+f"(c[2]), "+f"(c[3])
        : "r"(a[0]), "r"(a[1]), "r"(a[2]), "r"(a[3]), "r"(b[0]), "r"(b[1]));
}

#define LDSM4(r0, r1, r2, r3, addr) \
    asm volatile("ldmatrix.sync.aligned.m8n8.x4.shared.b16 {%0,%1,%2,%3}, [%4];" \
        : "=r"(r0), "=r"(r1), "=r"(r2), "=r"(r3) : "r"(addr))

// ============================================================
// Kernel 1: find agent, extract 5x5 patch (pad -1)
// ============================================================
__global__ void __launch_bounds__(256) patch_kernel(const float* __restrict__ x) {
    int w = threadIdx.x >> 5, lane = threadIdx.x & 31;
    int b = blockIdx.x * 8 + w;
    const float* xb = x + (size_t)b * 1024;
    int found = 0;
#pragma unroll
    for (int s = 0; s < 32; s++)
        if (xb[s * 32 + lane] == 3.0f) found = s * 32 + lane;
#pragma unroll
    for (int off = 16; off; off >>= 1)
        found = max(found, __shfl_xor_sync(0xffffffffu, found, off));
    int row = found >> 5, col = found & 31;
    if (lane < PIN) {
        int r = row + lane / 5 - 2;
        int c = col + lane % 5 - 2;
        float v = (r < 0 || r > 31 || c < 0 || c > 31) ? -1.0f : xb[r * 32 + c];
        g_patch[(size_t)b * PIN + lane] = v;
    }
}

// ============================================================
// Kernel 2: transpose W[l][k][n] -> g_wt[l][n][k] as fp16 (RN)
// ============================================================
__global__ void wtrans_kernel(const float* __restrict__ Wall) {
    __shared__ float t[32][33];
    const float* W = Wall + (size_t)blockIdx.z * HID * HID;
    __half* WT = g_wt + (size_t)blockIdx.z * HID * HID;
    int n0 = blockIdx.x * 32, k0 = blockIdx.y * 32;
    int tx = threadIdx.x, ty = threadIdx.y;
#pragma unroll
    for (int i = 0; i < 4; i++)
        t[ty + i * 8][tx] = W[(size_t)(k0 + ty + i * 8) * HID + n0 + tx];
    __syncthreads();
#pragma unroll
    for (int i = 0; i < 4; i++)
        WT[(size_t)(n0 + ty + i * 8) * HID + k0 + tx] = __float2half_rn(t[tx][ty + i * 8]);
}

// ============================================================
// Kernel 3: embed  h0 = patch . embed_W + embed_b  (K=25); writes fp32 + fp16
// ============================================================
__global__ void __launch_bounds__(256) embed_kernel(const float* __restrict__ eW,
                                                    const float* __restrict__ eb) {
    __shared__ float sp[64][PIN];
    int mb = blockIdx.y * 64, nb = blockIdx.x * 128;
    for (int i = threadIdx.x; i < 64 * PIN; i += 256)
        sp[i / PIN][i % PIN] = g_patch[(size_t)(mb + i / PIN) * PIN + i % PIN];
    __syncthreads();
    int col = threadIdx.x & 127, sg = threadIdx.x >> 7;
    float acc[32];
    float b = eb[nb + col];
#pragma unroll
    for (int s = 0; s < 32; s++) acc[s] = b;
    for (int k = 0; k < PIN; k++) {
        float w = eW[(size_t)k * HID + nb + col];
#pragma unroll
        for (int s = 0; s < 32; s++) acc[s] += sp[sg * 32 + s][k] * w;
    }
#pragma unroll
    for (int s = 0; s < 32; s++) {
        size_t idx = (size_t)(mb + sg * 32 + s) * HID + nb + col;
        g_h0[idx] = acc[s];
        g_ta0[idx] = __float2half_rn(acc[s]);
    }
}

// ============================================================
// Kernel 4: residual layer  C = A + relu(A @ W_l + b_l)
// mma.sync f16 m16n8k16, 256x128 CTA tile, 8 warps (4m x 2n) of 64x64,
// 4-stage cp.async pipeline, XOR-swizzled 128B rows, ldmatrix fragment
// loads with double-buffered fragment registers (prefetch ks+1 during ks).
// Warp tile 64x64 minimizes smem read bytes per MMA (smem-BW bound regime).
// ============================================================
__global__ void __launch_bounds__(NTHR, 1) gemm_kernel(int l, int dir,
                                                       const float* __restrict__ bias) {
    const float*  __restrict__ A  = dir ? g_h1  : g_h0;
    const __half* __restrict__ Ah = dir ? g_ta1 : g_ta0;
    float*        __restrict__ C  = dir ? g_h0  : g_h1;
    __half*       __restrict__ Ch = dir ? g_ta0 : g_ta1;
    const __half* __restrict__ W  = g_wt + (size_t)l * HID * HID;

    extern __shared__ char dynsmem[];
    uint32_t raw = smem_u32(dynsmem);
    uint32_t sbase = (raw + 1023u) & ~1023u;

    __shared__ float sbias[NT];

    int tid = threadIdx.x;
    int mbase = blockIdx.y * MT, nbase = blockIdx.x * NT;
    if (tid < NT) sbias[tid] = bias[nbase + tid];

    int wid = tid >> 5, lane = tid & 31;
    int wm = wid & 3, wn = wid >> 2;          // 4 m-warps x 2 n-warps
    int g = lane >> 2, t = lane & 3;

    // ldmatrix lane decomposition
    int rl  = lane & 7;                       // row within 8x8 matrix
    int sec = lane >> 3;                      // which 8x8 matrix this lane addresses
    int hi_a = sec >> 1;                      // A: k-chunk select (matrices 2,3)
    int r8_a = sec & 1;                       // A: row+8 select   (matrices 1,3)
    int hi_b = sec & 1;                       // B: k-chunk select (matrices 1,3)
    int nfo_b = sec >> 1;                     // B: second n-fragment (matrices 2,3)

    // per-lane row base addresses (bytes from stage base)
    uint32_t rowbase_a[4];
#pragma unroll
    for (int mf = 0; mf < 4; mf++)
        rowbase_a[mf] = (uint32_t)(wm * 64 + mf * 16 + r8_a * 8 + rl) * 128;
    uint32_t rowbase_b[4];
#pragma unroll
    for (int p = 0; p < 4; p++)
        rowbase_b[p] = (uint32_t)ABYTES
                     + (uint32_t)(wn * 64 + (2 * p + nfo_b) * 8 + rl) * 128;

    auto load_chunk = [&](int c) {
        int st = c & 3;
        uint32_t sa = sbase + st * STGB;
        uint32_t sb = sa + ABYTES;
        int kb = c * KC;
#pragma unroll
        for (int i = 0; i < 12; i++) {
            int idx = tid + i * NTHR;
            if (idx < 2048) {                 // A: 256 rows x 8 chunks of 8 fp16
                int r = idx >> 3, cid = idx & 7;
                cp_async16(sa + r * 128 + ((cid ^ (r & 7)) * 16),
                           Ah + (size_t)(mbase + r) * HID + kb + cid * 8);
            } else {                          // B: 128 rows x 8 chunks
                int j = idx - 2048;
                int r = j >> 3, cid = j & 7;
                cp_async16(sb + r * 128 + ((cid ^ (r & 7)) * 16),
                           W + (size_t)(nbase + r) * HID + kb + cid * 8);
            }
        }
    };

    float acc[4][8][4];
#pragma unroll
    for (int i = 0; i < 4; i++)
#pragma unroll
        for (int j = 0; j < 8; j++)
#pragma unroll
            for (int q = 0; q < 4; q++) acc[i][j][q] = 0.0f;

    uint32_t fa[2][4][4], fb[2][8][2];

    auto ldfrag = [&](uint32_t stb, int ks, int buf) {
        uint32_t offa = (uint32_t)((((2 * ks) | hi_a) ^ rl) * 16);
        uint32_t offb = (uint32_t)((((2 * ks) | hi_b) ^ rl) * 16);
#pragma unroll
        for (int mf = 0; mf < 4; mf++)
            LDSM4(fa[buf][mf][0], fa[buf][mf][1], fa[buf][mf][2], fa[buf][mf][3],
                  stb + rowbase_a[mf] + offa);
#pragma unroll
        for (int p = 0; p < 4; p++)
            LDSM4(fb[buf][2 * p][0], fb[buf][2 * p][1],
                  fb[buf][2 * p + 1][0], fb[buf][2 * p + 1][1],
                  stb + rowbase_b[p] + offb);
    };

    // prologue: stages 0..2
    for (int c = 0; c < 3; c++) {
        load_chunk(c);
        asm volatile("cp.async.commit_group;" ::: "memory");
    }

    for (int c = 0; c < NCH; c++) {
        asm volatile("cp.async.wait_group 2;" ::: "memory");
        __syncthreads();
        uint32_t stb = sbase + (c & 3) * STGB;
        ldfrag(stb, 0, 0);
        int nc = c + 3;
        if (nc < NCH) load_chunk(nc);
        asm volatile("cp.async.commit_group;" ::: "memory");

#pragma unroll
        for (int ks = 0; ks < 4; ks++) {
            if (ks < 3) ldfrag(stb, ks + 1, (ks + 1) & 1);
            int cur = ks & 1;
#pragma unroll
            for (int mf = 0; mf < 4; mf++)
#pragma unroll
                for (int nf = 0; nf < 8; nf++)
                    mma_f16(acc[mf][nf], fa[cur][mf], fb[cur][nf]);
        }
    }
    asm volatile("cp.async.wait_group 0;" ::: "memory");

    // epilogue: bias + relu + residual; write exact fp32 and rounded fp16
    int mb0 = mbase + wm * 64, nb0 = nbase + wn * 64;
#pragma unroll
    for (int mf = 0; mf < 4; mf++) {
#pragma unroll
        for (int half = 0; half < 2; half++) {
            int row = mb0 + mf * 16 + half * 8 + g;
            const float* Ar = A + (size_t)row * HID + nb0;
            float* Cr = C + (size_t)row * HID + nb0;
            __half* Chr = Ch + (size_t)row * HID + nb0;
#pragma unroll
            for (int nf = 0; nf < 8; nf++) {
                int cl = nf * 8 + 2 * t;
                float2 res = *(const float2*)(Ar + cl);
                float b0 = sbias[wn * 64 + cl];
                float b1 = sbias[wn * 64 + cl + 1];
                float v0 = acc[mf][nf][half * 2 + 0];
                float v1 = acc[mf][nf][half * 2 + 1];
                float2 o;
                o.x = res.x + fmaxf(v0 + b0, 0.0f);
                o.y = res.y + fmaxf(v1 + b1, 0.0f);
                *(float2*)(Cr + cl) = o;
                *(__half2*)(Chr + cl) = __floats2half2_rn(o.x, o.y);
            }
        }
    }
}

// ============================================================
// Kernel 5: LayerNorm + head (N=4). One warp per row. Reads exact fp32.
// ============================================================
__global__ void __launch_bounds__(256) head_kernel(const float* __restrict__ lng,
                                                   const float* __restrict__ lnb,
                                                   const float* __restrict__ hW,
                                                   const float* __restrict__ hb,
                                                   float* __restrict__ out) {
    int w = threadIdx.x >> 5, lane = threadIdx.x & 31;
    int row = blockIdx.x * 8 + w;
    const float4* h4 = (const float4*)(g_h0 + (size_t)row * HID);
    float4 v[16];
    float s = 0.f, ss = 0.f;
#pragma unroll
    for (int i = 0; i < 16; i++) {
        v[i] = h4[i * 32 + lane];
        s += v[i].x + v[i].y + v[i].z + v[i].w;
        ss += v[i].x * v[i].x + v[i].y * v[i].y + v[i].z * v[i].z + v[i].w * v[i].w;
    }
#pragma unroll
    for (int off = 16; off; off >>= 1) {
        s += __shfl_xor_sync(0xffffffffu, s, off);
        ss += __shfl_xor_sync(0xffffffffu, ss, off);
    }
    float mu = s * (1.0f / HID);
    float var = ss * (1.0f / HID) - mu * mu;
    float rs = rsqrtf(var + 1e-5f);
    float a0 = 0.f, a1 = 0.f, a2 = 0.f, a3 = 0.f;
    const float4* g4 = (const float4*)lng;
    const float4* b4 = (const float4*)lnb;
    const float4* w4 = (const float4*)hW;
#pragma unroll 1
    for (int i = 0; i < 16; i++) {
        int k4 = i * 32 + lane;
        float4 gg = g4[k4], bb = b4[k4];
        float hn[4];
        hn[0] = (v[i].x - mu) * rs * gg.x + bb.x;
        hn[1] = (v[i].y - mu) * rs * gg.y + bb.y;
        hn[2] = (v[i].z - mu) * rs * gg.z + bb.z;
        hn[3] = (v[i].w - mu) * rs * gg.w + bb.w;
#pragma unroll
        for (int j = 0; j < 4; j++) {
            float4 wr = w4[k4 * 4 + j];
            a0 += hn[j] * wr.x;
            a1 += hn[j] * wr.y;
            a2 += hn[j] * wr.z;
            a3 += hn[j] * wr.w;
        }
    }
#pragma unroll
    for (int off = 16; off; off >>= 1) {
        a0 += __shfl_xor_sync(0xffffffffu, a0, off);
        a1 += __shfl_xor_sync(0xffffffffu, a1, off);
        a2 += __shfl_xor_sync(0xffffffffu, a2, off);
        a3 += __shfl_xor_sync(0xffffffffu, a3, off);
    }
    if (lane == 0) {
        float4 hbv = *(const float4*)hb;
        float4 o;
        o.x = a0 + hbv.x; o.y = a1 + hbv.y; o.z = a2 + hbv.z; o.w = a3 + hbv.w;
        ((float4*)out)[row] = o;
    }
}

// ============================================================
extern "C" void kernel_launch(void* const* d_in, const int* in_sizes, int n_in,
                              void* d_out, int out_size) {
    const float* x   = (const float*)d_in[0];
    const float* eW  = (const float*)d_in[1];
    const float* eb  = (const float*)d_in[2];
    const float* lW  = (const float*)d_in[3];
    const float* lb  = (const float*)d_in[4];
    const float* lng = (const float*)d_in[5];
    const float* lnb = (const float*)d_in[6];
    const float* hW  = (const float*)d_in[7];
    const float* hb  = (const float*)d_in[8];

    cudaFuncSetAttribute(gemm_kernel, cudaFuncAttributeMaxDynamicSharedMemorySize, DYNSMEM);

    patch_kernel<<<BATCH / 8, 256>>>(x);
    wtrans_kernel<<<dim3(HID / 32, HID / 32, NLAYER), dim3(32, 8)>>>(lW);
    embed_kernel<<<dim3(HID / 128, BATCH / 64), 256>>>(eW, eb);
    for (int l = 0; l < NLAYER; l++)
        gemm_kernel<<<dim3(HID / NT, BATCH / MT), NTHR, DYNSMEM>>>(l, l & 1, lb + (size_t)l * HID);
    head_kernel<<<BATCH / 8, 256>>>(lng, lnb, hW, hb, (float*)d_out);
}

// round 8
// speedup vs baseline: 1.0420x; 1.0420x over previous
#include <cuda_runtime.h>
#include <cuda_fp16.h>
#include <cstdint>
#include <cstddef>

#define BATCH   16384
#define HID     2048
#define NLAYER  8
#define PIN     25

#define MT      256
#define NT      128
#define KC      64                  // 64 fp16 k-values = 128B per row
#define NCH     (HID / KC)          // 32
#define ABYTES  (MT * 128)          // 32768
#define BBYTES  (NT * 128)          // 16384
#define STGB    (ABYTES + BBYTES)   // 49152
#define DYNSMEM (4 * STGB + 1024)   // 197632
#define NTHR    256

// ---------------- device scratch (allocation-free) ----------------
__device__ float  g_h0[(size_t)BATCH * HID];     // exact fp32 activations
__device__ float  g_h1[(size_t)BATCH * HID];
__device__ __half g_ta0[(size_t)BATCH * HID];    // fp16-rounded MMA copies
__device__ __half g_ta1[(size_t)BATCH * HID];
__device__ __half g_wt[(size_t)NLAYER * HID * HID];  // W^T fp16 [l][n][k]
__device__ float  g_patch[(size_t)BATCH * PIN];

// ---------------- helpers ----------------
__device__ __forceinline__ uint32_t smem_u32(const void* p) {
    uint32_t a;
    asm("{ .reg .u64 t; cvta.to.shared.u64 t, %1; cvt.u32.u64 %0, t; }" : "=r"(a) : "l"(p));
    return a;
}

__device__ __forceinline__ void cp_async16(uint32_t s, const void* g) {
    asm volatile("cp.async.cg.shared.global [%0], [%1], 16;" :: "r"(s), "l"(g) : "memory");
}

__device__ __forceinline__ void mma_f16(float* c, const uint32_t* a, const uint32_t* b) {
    asm volatile(
        "mma.sync.aligned.m16n8k16.row.col.f32.f16.f16.f32 "
        "{%0,%1,%2,%3}, {%4,%5,%6,%7}, {%8,%9}, {%0,%1,%2,%3};"
        : "+f"(c[0]), "+f"(c[1]), "+f"(c[2]), "+f"(c[3])
        : "r"(a[0]), "r"(a[1]), "r"(a[2]), "r"(a[3]), "r"(b[0]), "r"(b[1]));
}

#define LDSM4(r0, r1, r2, r3, addr) \
    asm volatile("ldmatrix.sync.aligned.m8n8.x4.shared.b16 {%0,%1,%2,%3}, [%4];" \
        : "=r"(r0), "=r"(r1), "=r"(r2), "=r"(r3) : "r"(addr))

// ============================================================
// Kernel 1: find agent, extract 5x5 patch (pad -1)
// ============================================================
__global__ void __launch_bounds__(256) patch_kernel(const float* __restrict__ x) {
    int w = threadIdx.x >> 5, lane = threadIdx.x & 31;
    int b = blockIdx.x * 8 + w;
    const float* xb = x + (size_t)b * 1024;
    int found = 0;
#pragma unroll
    for (int s = 0; s < 32; s++)
        if (xb[s * 32 + lane] == 3.0f) found = s * 32 + lane;
#pragma unroll
    for (int off = 16; off; off >>= 1)
        found = max(found, __shfl_xor_sync(0xffffffffu, found, off));
    int row = found >> 5, col = found & 31;
    if (lane < PIN) {
        int r = row + lane / 5 - 2;
        int c = col + lane % 5 - 2;
        float v = (r < 0 || r > 31 || c < 0 || c > 31) ? -1.0f : xb[r * 32 + c];
        g_patch[(size_t)b * PIN + lane] = v;
    }
}

// ============================================================
// Kernel 2: transpose W[l][k][n] -> g_wt[l][n][k] as fp16 (RN)
// ============================================================
__global__ void wtrans_kernel(const float* __restrict__ Wall) {
    __shared__ float t[32][33];
    const float* W = Wall + (size_t)blockIdx.z * HID * HID;
    __half* WT = g_wt + (size_t)blockIdx.z * HID * HID;
    int n0 = blockIdx.x * 32, k0 = blockIdx.y * 32;
    int tx = threadIdx.x, ty = threadIdx.y;
#pragma unroll
    for (int i = 0; i < 4; i++)
        t[ty + i * 8][tx] = W[(size_t)(k0 + ty + i * 8) * HID + n0 + tx];
    __syncthreads();
#pragma unroll
    for (int i = 0; i < 4; i++)
        WT[(size_t)(n0 + ty + i * 8) * HID + k0 + tx] = __float2half_rn(t[tx][ty + i * 8]);
}

// ============================================================
// Kernel 3: embed  h0 = patch . embed_W + embed_b  (K=25); writes fp32 + fp16
// ============================================================
__global__ void __launch_bounds__(256) embed_kernel(const float* __restrict__ eW,
                                                    const float* __restrict__ eb) {
    __shared__ float sp[64][PIN];
    int mb = blockIdx.y * 64, nb = blockIdx.x * 128;
    for (int i = threadIdx.x; i < 64 * PIN; i += 256)
        sp[i / PIN][i % PIN] = g_patch[(size_t)(mb + i / PIN) * PIN + i % PIN];
    __syncthreads();
    int col = threadIdx.x & 127, sg = threadIdx.x >> 7;
    float acc[32];
    float b = eb[nb + col];
#pragma unroll
    for (int s = 0; s < 32; s++) acc[s] = b;
    for (int k = 0; k < PIN; k++) {
        float w = eW[(size_t)k * HID + nb + col];
#pragma unroll
        for (int s = 0; s < 32; s++) acc[s] += sp[sg * 32 + s][k] * w;
    }
#pragma unroll
    for (int s = 0; s < 32; s++) {
        size_t idx = (size_t)(mb + sg * 32 + s) * HID + nb + col;
        g_h0[idx] = acc[s];
        g_ta0[idx] = __float2half_rn(acc[s]);
    }
}

// ============================================================
// Kernel 4: residual layer  C = A + relu(A @ W_l + b_l)
// mma.sync f16 m16n8k16, 256x128 CTA tile, 8 warps (4m x 2n) of 64x64.
// Cross-chunk software pipeline: wait_group 1 guarantees chunks c AND c+1
// resident; chunk c+1's first fragments are prefetched during chunk c's
// last ks-step, so post-barrier execution starts with MMAs from registers.
// ============================================================
__global__ void __launch_bounds__(NTHR, 1) gemm_kernel(int l, int dir,
                                                       const float* __restrict__ bias) {
    const float*  __restrict__ A  = dir ? g_h1  : g_h0;
    const __half* __restrict__ Ah = dir ? g_ta1 : g_ta0;
    float*        __restrict__ C  = dir ? g_h0  : g_h1;
    __half*       __restrict__ Ch = dir ? g_ta0 : g_ta1;
    const __half* __restrict__ W  = g_wt + (size_t)l * HID * HID;

    extern __shared__ char dynsmem[];
    uint32_t raw = smem_u32(dynsmem);
    uint32_t sbase = (raw + 1023u) & ~1023u;

    __shared__ float sbias[NT];

    int tid = threadIdx.x;
    int mbase = blockIdx.y * MT, nbase = blockIdx.x * NT;
    if (tid < NT) sbias[tid] = bias[nbase + tid];

    int wid = tid >> 5, lane = tid & 31;
    int wm = wid & 3, wn = wid >> 2;          // 4 m-warps x 2 n-warps
    int g = lane >> 2, t = lane & 3;

    // ldmatrix lane decomposition
    int rl  = lane & 7;
    int sec = lane >> 3;
    int hi_a = sec >> 1;
    int r8_a = sec & 1;
    int hi_b = sec & 1;
    int nfo_b = sec >> 1;

    uint32_t rowbase_a[4];
#pragma unroll
    for (int mf = 0; mf < 4; mf++)
        rowbase_a[mf] = (uint32_t)(wm * 64 + mf * 16 + r8_a * 8 + rl) * 128;
    uint32_t rowbase_b[4];
#pragma unroll
    for (int p = 0; p < 4; p++)
        rowbase_b[p] = (uint32_t)ABYTES
                     + (uint32_t)(wn * 64 + (2 * p + nfo_b) * 8 + rl) * 128;

    auto load_chunk = [&](int c) {
        int st = c & 3;
        uint32_t sa = sbase + st * STGB;
        uint32_t sb = sa + ABYTES;
        int kb = c * KC;
#pragma unroll
        for (int i = 0; i < 12; i++) {
            int idx = tid + i * NTHR;
            if (idx < 2048) {
                int r = idx >> 3, cid = idx & 7;
                cp_async16(sa + r * 128 + ((cid ^ (r & 7)) * 16),
                           Ah + (size_t)(mbase + r) * HID + kb + cid * 8);
            } else {
                int j = idx - 2048;
                int r = j >> 3, cid = j & 7;
                cp_async16(sb + r * 128 + ((cid ^ (r & 7)) * 16),
                           W + (size_t)(nbase + r) * HID + kb + cid * 8);
            }
        }
    };

    float acc[4][8][4];
#pragma unroll
    for (int i = 0; i < 4; i++)
#pragma unroll
        for (int j = 0; j < 8; j++)
#pragma unroll
            for (int q = 0; q < 4; q++) acc[i][j][q] = 0.0f;

    uint32_t fa[2][4][4], fb[2][8][2];

    auto ldfrag = [&](uint32_t stb, int ks, int buf) {
        uint32_t offa = (uint32_t)((((2 * ks) | hi_a) ^ rl) * 16);
        uint32_t offb = (uint32_t)((((2 * ks) | hi_b) ^ rl) * 16);
#pragma unroll
        for (int mf = 0; mf < 4; mf++)
            LDSM4(fa[buf][mf][0], fa[buf][mf][1], fa[buf][mf][2], fa[buf][mf][3],
                  stb + rowbase_a[mf] + offa);
#pragma unroll
        for (int p = 0; p < 4; p++)
            LDSM4(fb[buf][2 * p][0], fb[buf][2 * p][1],
                  fb[buf][2 * p + 1][0], fb[buf][2 * p + 1][1],
                  stb + rowbase_b[p] + offb);
    };

    // prologue: load chunks 0..2 (one group each); wait until 0 AND 1 resident
    for (int c = 0; c < 3; c++) {
        load_chunk(c);
        asm volatile("cp.async.commit_group;" ::: "memory");
    }
    asm volatile("cp.async.wait_group 1;" ::: "memory");
    __syncthreads();
    ldfrag(sbase, 0, 0);   // chunk 0, ks 0 -> buf 0

    for (int c = 0; c < NCH; c++) {
        uint32_t stb  = sbase + (c & 3) * STGB;
        uint32_t stb1 = sbase + ((c + 1) & 3) * STGB;
        int nc = c + 3;
        if (nc < NCH) load_chunk(nc);          // stage (c-1)&3: freed by barrier below
        asm volatile("cp.async.commit_group;" ::: "memory");

#pragma unroll
        for (int ks = 0; ks < 4; ks++) {
            int cur = ks & 1;
            if (ks < 3) ldfrag(stb, ks + 1, (ks + 1) & 1);
            else if (c + 1 < NCH) ldfrag(stb1, 0, 0);   // next chunk's first frags
#pragma unroll
            for (int mf = 0; mf < 4; mf++)
#pragma unroll
                for (int nf = 0; nf < 8; nf++)
                    mma_f16(acc[mf][nf], fa[cur][mf], fb[cur][nf]);
        }

        if (c + 1 < NCH) {
            // guarantee chunks c+1 AND c+2 resident for next iteration;
            // barrier frees stage (c)&3 for the load at iteration c+1... (c+4)
            asm volatile("cp.async.wait_group 1;" ::: "memory");
            __syncthreads();
        }
    }
    asm volatile("cp.async.wait_group 0;" ::: "memory");

    // epilogue: bias + relu + residual; write exact fp32 and rounded fp16
    int mb0 = mbase + wm * 64, nb0 = nbase + wn * 64;
#pragma unroll
    for (int mf = 0; mf < 4; mf++) {
#pragma unroll
        for (int half = 0; half < 2; half++) {
            int row = mb0 + mf * 16 + half * 8 + g;
            const float* Ar = A + (size_t)row * HID + nb0;
            float* Cr = C + (size_t)row * HID + nb0;
            __half* Chr = Ch + (size_t)row * HID + nb0;
#pragma unroll
            for (int nf = 0; nf < 8; nf++) {
                int cl = nf * 8 + 2 * t;
                float2 res = *(const float2*)(Ar + cl);
                float b0 = sbias[wn * 64 + cl];
                float b1 = sbias[wn * 64 + cl + 1];
                float v0 = acc[mf][nf][half * 2 + 0];
                float v1 = acc[mf][nf][half * 2 + 1];
                float2 o;
                o.x = res.x + fmaxf(v0 + b0, 0.0f);
                o.y = res.y + fmaxf(v1 + b1, 0.0f);
                *(float2*)(Cr + cl) = o;
                *(__half2*)(Chr + cl) = __floats2half2_rn(o.x, o.y);
            }
        }
    }
}

// ============================================================
// Kernel 5: LayerNorm + head (N=4). One warp per row. Reads exact fp32.
// ============================================================
__global__ void __launch_bounds__(256) head_kernel(const float* __restrict__ lng,
                                                   const float* __restrict__ lnb,
                                                   const float* __restrict__ hW,
                                                   const float* __restrict__ hb,
                                                   float* __restrict__ out) {
    int w = threadIdx.x >> 5, lane = threadIdx.x & 31;
    int row = blockIdx.x * 8 + w;
    const float4* h4 = (const float4*)(g_h0 + (size_t)row * HID);
    float4 v[16];
    float s = 0.f, ss = 0.f;
#pragma unroll
    for (int i = 0; i < 16; i++) {
        v[i] = h4[i * 32 + lane];
        s += v[i].x + v[i].y + v[i].z + v[i].w;
        ss += v[i].x * v[i].x + v[i].y * v[i].y + v[i].z * v[i].z + v[i].w * v[i].w;
    }
#pragma unroll
    for (int off = 16; off; off >>= 1) {
        s += __shfl_xor_sync(0xffffffffu, s, off);
        ss += __shfl_xor_sync(0xffffffffu, ss, off);
    }
    float mu = s * (1.0f / HID);
    float var = ss * (1.0f / HID) - mu * mu;
    float rs = rsqrtf(var + 1e-5f);
    float a0 = 0.f, a1 = 0.f, a2 = 0.f, a3 = 0.f;
    const float4* g4 = (const float4*)lng;
    const float4* b4 = (const float4*)lnb;
    const float4* w4 = (const float4*)hW;
#pragma unroll 1
    for (int i = 0; i < 16; i++) {
        int k4 = i * 32 + lane;
        float4 gg = g4[k4], bb = b4[k4];
        float hn[4];
        hn[0] = (v[i].x - mu) * rs * gg.x + bb.x;
        hn[1] = (v[i].y - mu) * rs * gg.y + bb.y;
        hn[2] = (v[i].z - mu) * rs * gg.z + bb.z;
        hn[3] = (v[i].w - mu) * rs * gg.w + bb.w;
#pragma unroll
        for (int j = 0; j < 4; j++) {
            float4 wr = w4[k4 * 4 + j];
            a0 += hn[j] * wr.x;
            a1 += hn[j] * wr.y;
            a2 += hn[j] * wr.z;
            a3 += hn[j] * wr.w;
        }
    }
#pragma unroll
    for (int off = 16; off; off >>= 1) {
        a0 += __shfl_xor_sync(0xffffffffu, a0, off);
        a1 += __shfl_xor_sync(0xffffffffu, a1, off);
        a2 += __shfl_xor_sync(0xffffffffu, a2, off);
        a3 += __shfl_xor_sync(0xffffffffu, a3, off);
    }
    if (lane == 0) {
        float4 hbv = *(const float4*)hb;
        float4 o;
        o.x = a0 + hbv.x; o.y = a1 + hbv.y; o.z = a2 + hbv.z; o.w = a3 + hbv.w;
        ((float4*)out)[row] = o;
    }
}

// ============================================================
extern "C" void kernel_launch(void* const* d_in, const int* in_sizes, int n_in,
                              void* d_out, int out_size) {
    const float* x   = (const float*)d_in[0];
    const float* eW  = (const float*)d_in[1];
    const float* eb  = (const float*)d_in[2];
    const float* lW  = (const float*)d_in[3];
    const float* lb  = (const float*)d_in[4];
    const float* lng = (const float*)d_in[5];
    const float* lnb = (const float*)d_in[6];
    const float* hW  = (const float*)d_in[7];
    const float* hb  = (const float*)d_in[8];

    cudaFuncSetAttribute(gemm_kernel, cudaFuncAttributeMaxDynamicSharedMemorySize, DYNSMEM);

    patch_kernel<<<BATCH / 8, 256>>>(x);
    wtrans_kernel<<<dim3(HID / 32, HID / 32, NLAYER), dim3(32, 8)>>>(lW);
    embed_kernel<<<dim3(HID / 128, BATCH / 64), 256>>>(eW, eb);
    for (int l = 0; l < NLAYER; l++)
        gemm_kernel<<<dim3(HID / NT, BATCH / MT), NTHR, DYNSMEM>>>(l, l & 1, lb + (size_t)l * HID);
    head_kernel<<<BATCH / 8, 256>>>(lng, lnb, hW, hb, (float*)d_out);
}

// round 9
// speedup vs baseline: 1.2634x; 1.2125x over previous
#include <cuda_runtime.h>
#include <cuda_fp16.h>
#include <cstdint>
#include <cstddef>

#define BATCH   16384
#define HID     2048
#define NLAYER  8
#define PIN     25

#define MT      128
#define NT      128
#define KC      64                  // 64 fp16 k-values = 128B per row
#define NCH     (HID / KC)          // 32
#define NSTG    3
#define ABYTES  (MT * 128)          // 16384
#define BBYTES  (NT * 128)          // 16384
#define STGB    (ABYTES + BBYTES)   // 32768
#define DYNSMEM (NSTG * STGB + 1024) // 99328  (x2 CTAs = 194.5KB/SM)
#define NTHR    256

// ---------------- device scratch (allocation-free) ----------------
__device__ float  g_h0[(size_t)BATCH * HID];     // exact fp32 activations
__device__ float  g_h1[(size_t)BATCH * HID];
__device__ __half g_ta0[(size_t)BATCH * HID];    // fp16-rounded MMA copies
__device__ __half g_ta1[(size_t)BATCH * HID];
__device__ __half g_wt[(size_t)NLAYER * HID * HID];  // W^T fp16 [l][n][k]
__device__ float  g_patch[(size_t)BATCH * PIN];

// ---------------- helpers ----------------
__device__ __forceinline__ uint32_t smem_u32(const void* p) {
    uint32_t a;
    asm("{ .reg .u64 t; cvta.to.shared.u64 t, %1; cvt.u32.u64 %0, t; }" : "=r"(a) : "l"(p));
    return a;
}

__device__ __forceinline__ void cp_async16(uint32_t s, const void* g) {
    asm volatile("cp.async.cg.shared.global [%0], [%1], 16;" :: "r"(s), "l"(g) : "memory");
}

__device__ __forceinline__ void mma_f16(float* c, const uint32_t* a, const uint32_t* b) {
    asm volatile(
        "mma.sync.aligned.m16n8k16.row.col.f32.f16.f16.f32 "
        "{%0,%1,%2,%3}, {%4,%5,%6,%7}, {%8,%9}, {%0,%1,%2,%3};"
        : "+f"(c[0]), "+f"(c[1]), "+f"(c[2]), "+f"(c[3])
        : "r"(a[0]), "r"(a[1]), "r"(a[2]), "r"(a[3]), "r"(b[0]), "r"(b[1]));
}

#define LDSM4(r0, r1, r2, r3, addr) \
    asm volatile("ldmatrix.sync.aligned.m8n8.x4.shared.b16 {%0,%1,%2,%3}, [%4];" \
        : "=r"(r0), "=r"(r1), "=r"(r2), "=r"(r3) : "r"(addr))

// ============================================================
// Kernel 1: find agent, extract 5x5 patch (pad -1)
// ============================================================
__global__ void __launch_bounds__(256) patch_kernel(const float* __restrict__ x) {
    int w = threadIdx.x >> 5, lane = threadIdx.x & 31;
    int b = blockIdx.x * 8 + w;
    const float* xb = x + (size_t)b * 1024;
    int found = 0;
#pragma unroll
    for (int s = 0; s < 32; s++)
        if (xb[s * 32 + lane] == 3.0f) found = s * 32 + lane;
#pragma unroll
    for (int off = 16; off; off >>= 1)
        found = max(found, __shfl_xor_sync(0xffffffffu, found, off));
    int row = found >> 5, col = found & 31;
    if (lane < PIN) {
        int r = row + lane / 5 - 2;
        int c = col + lane % 5 - 2;
        float v = (r < 0 || r > 31 || c < 0 || c > 31) ? -1.0f : xb[r * 32 + c];
        g_patch[(size_t)b * PIN + lane] = v;
    }
}

// ============================================================
// Kernel 2: transpose W[l][k][n] -> g_wt[l][n][k] as fp16 (RN)
// ============================================================
__global__ void wtrans_kernel(const float* __restrict__ Wall) {
    __shared__ float t[32][33];
    const float* W = Wall + (size_t)blockIdx.z * HID * HID;
    __half* WT = g_wt + (size_t)blockIdx.z * HID * HID;
    int n0 = blockIdx.x * 32, k0 = blockIdx.y * 32;
    int tx = threadIdx.x, ty = threadIdx.y;
#pragma unroll
    for (int i = 0; i < 4; i++)
        t[ty + i * 8][tx] = W[(size_t)(k0 + ty + i * 8) * HID + n0 + tx];
    __syncthreads();
#pragma unroll
    for (int i = 0; i < 4; i++)
        WT[(size_t)(n0 + ty + i * 8) * HID + k0 + tx] = __float2half_rn(t[tx][ty + i * 8]);
}

// ============================================================
// Kernel 3: embed  h0 = patch . embed_W + embed_b  (K=25); writes fp32 + fp16
// ============================================================
__global__ void __launch_bounds__(256) embed_kernel(const float* __restrict__ eW,
                                                    const float* __restrict__ eb) {
    __shared__ float sp[64][PIN];
    int mb = blockIdx.y * 64, nb = blockIdx.x * 128;
    for (int i = threadIdx.x; i < 64 * PIN; i += 256)
        sp[i / PIN][i % PIN] = g_patch[(size_t)(mb + i / PIN) * PIN + i % PIN];
    __syncthreads();
    int col = threadIdx.x & 127, sg = threadIdx.x >> 7;
    float acc[32];
    float b = eb[nb + col];
#pragma unroll
    for (int s = 0; s < 32; s++) acc[s] = b;
    for (int k = 0; k < PIN; k++) {
        float w = eW[(size_t)k * HID + nb + col];
#pragma unroll
        for (int s = 0; s < 32; s++) acc[s] += sp[sg * 32 + s][k] * w;
    }
#pragma unroll
    for (int s = 0; s < 32; s++) {
        size_t idx = (size_t)(mb + sg * 32 + s) * HID + nb + col;
        g_h0[idx] = acc[s];
        g_ta0[idx] = __float2half_rn(acc[s]);
    }
}

// ============================================================
// Kernel 4: residual layer  C = A + relu(A @ W_l + b_l)
// mma.sync f16 m16n8k16, 128x128 CTA tile, 8 warps (2m x 4n) of 64x32,
// 3-stage cp.async pipeline, 97KB smem/CTA -> 2 CTAs per SM (32 warps/SM).
// Two independent barrier domains hide each other's chunk-boundary stalls.
// ============================================================
__global__ void __launch_bounds__(NTHR, 2) gemm_kernel(int l, int dir,
                                                       const float* __restrict__ bias) {
    const float*  __restrict__ A  = dir ? g_h1  : g_h0;
    const __half* __restrict__ Ah = dir ? g_ta1 : g_ta0;
    float*        __restrict__ C  = dir ? g_h0  : g_h1;
    __half*       __restrict__ Ch = dir ? g_ta0 : g_ta1;
    const __half* __restrict__ W  = g_wt + (size_t)l * HID * HID;

    extern __shared__ char dynsmem[];
    uint32_t raw = smem_u32(dynsmem);
    uint32_t sbase = (raw + 1023u) & ~1023u;

    __shared__ float sbias[NT];

    int tid = threadIdx.x;
    int mbase = blockIdx.y * MT, nbase = blockIdx.x * NT;
    if (tid < NT) sbias[tid] = bias[nbase + tid];

    int wid = tid >> 5, lane = tid & 31;
    int wm = wid & 1, wn = wid >> 1;          // 2 m-warps x 4 n-warps
    int g = lane >> 2, t = lane & 3;

    // ldmatrix lane decomposition
    int rl  = lane & 7;                       // row within 8x8 matrix
    int sec = lane >> 3;                      // which 8x8 matrix this lane addresses
    int hi_a = sec >> 1;                      // A: k-chunk select (matrices 2,3)
    int r8_a = sec & 1;                       // A: row+8 select   (matrices 1,3)
    int hi_b = sec & 1;                       // B: k-chunk select (matrices 1,3)
    int nfo_b = sec >> 1;                     // B: second n-fragment (matrices 2,3)

    uint32_t rowbase_a[4];
#pragma unroll
    for (int mf = 0; mf < 4; mf++)
        rowbase_a[mf] = (uint32_t)(wm * 64 + mf * 16 + r8_a * 8 + rl) * 128;
    uint32_t rowbase_b[2];
#pragma unroll
    for (int p = 0; p < 2; p++)
        rowbase_b[p] = (uint32_t)ABYTES
                     + (uint32_t)(wn * 32 + (2 * p + nfo_b) * 8 + rl) * 128;

    auto load_chunk = [&](int c) {
        uint32_t sa = sbase + (uint32_t)(c % NSTG) * STGB;
        uint32_t sb = sa + ABYTES;
        int kb = c * KC;
#pragma unroll
        for (int i = 0; i < 8; i++) {
            int idx = tid + i * NTHR;
            if (idx < 1024) {                 // A: 128 rows x 8 chunks of 8 fp16
                int r = idx >> 3, cid = idx & 7;
                cp_async16(sa + r * 128 + ((cid ^ (r & 7)) * 16),
                           Ah + (size_t)(mbase + r) * HID + kb + cid * 8);
            } else {                          // B: 128 rows x 8 chunks
                int j = idx - 1024;
                int r = j >> 3, cid = j & 7;
                cp_async16(sb + r * 128 + ((cid ^ (r & 7)) * 16),
                           W + (size_t)(nbase + r) * HID + kb + cid * 8);
            }
        }
    };

    float acc[4][4][4];
#pragma unroll
    for (int i = 0; i < 4; i++)
#pragma unroll
        for (int j = 0; j < 4; j++)
#pragma unroll
            for (int q = 0; q < 4; q++) acc[i][j][q] = 0.0f;

    // prologue: load chunks 0,1
    for (int c = 0; c < 2; c++) {
        load_chunk(c);
        asm volatile("cp.async.commit_group;" ::: "memory");
    }

    for (int c = 0; c < NCH; c++) {
        asm volatile("cp.async.wait_group 1;" ::: "memory");   // chunk c resident
        __syncthreads();                                        // all warps see it; stage (c+2)%3 free
        uint32_t stb = sbase + (uint32_t)(c % NSTG) * STGB;
        int nc = c + 2;
        if (nc < NCH) load_chunk(nc);
        asm volatile("cp.async.commit_group;" ::: "memory");

#pragma unroll
        for (int ks = 0; ks < 4; ks++) {
            uint32_t offa = (uint32_t)((((2 * ks) | hi_a) ^ rl) * 16);
            uint32_t offb = (uint32_t)((((2 * ks) | hi_b) ^ rl) * 16);
            uint32_t fa[4][4], fb[4][2];
#pragma unroll
            for (int mf = 0; mf < 4; mf++)
                LDSM4(fa[mf][0], fa[mf][1], fa[mf][2], fa[mf][3],
                      stb + rowbase_a[mf] + offa);
#pragma unroll
            for (int p = 0; p < 2; p++)
                LDSM4(fb[2 * p][0], fb[2 * p][1], fb[2 * p + 1][0], fb[2 * p + 1][1],
                      stb + rowbase_b[p] + offb);
#pragma unroll
            for (int mf = 0; mf < 4; mf++)
#pragma unroll
                for (int nf = 0; nf < 4; nf++)
                    mma_f16(acc[mf][nf], fa[mf], fb[nf]);
        }
    }
    asm volatile("cp.async.wait_group 0;" ::: "memory");

    // epilogue: bias + relu + residual; write exact fp32 and rounded fp16
    int mb0 = mbase + wm * 64, nb0 = nbase + wn * 32;
#pragma unroll
    for (int mf = 0; mf < 4; mf++) {
#pragma unroll
        for (int half = 0; half < 2; half++) {
            int row = mb0 + mf * 16 + half * 8 + g;
            const float* Ar = A + (size_t)row * HID + nb0;
            float* Cr = C + (size_t)row * HID + nb0;
            __half* Chr = Ch + (size_t)row * HID + nb0;
#pragma unroll
            for (int nf = 0; nf < 4; nf++) {
                int cl = nf * 8 + 2 * t;
                float2 res = *(const float2*)(Ar + cl);
                float b0 = sbias[wn * 32 + cl];
                float b1 = sbias[wn * 32 + cl + 1];
                float v0 = acc[mf][nf][half * 2 + 0];
                float v1 = acc[mf][nf][half * 2 + 1];
                float2 o;
                o.x = res.x + fmaxf(v0 + b0, 0.0f);
                o.y = res.y + fmaxf(v1 + b1, 0.0f);
                *(float2*)(Cr + cl) = o;
                *(__half2*)(Chr + cl) = __floats2half2_rn(o.x, o.y);
            }
        }
    }
}

// ============================================================
// Kernel 5: LayerNorm + head (N=4). One warp per row. Reads exact fp32.
// ============================================================
__global__ void __launch_bounds__(256) head_kernel(const float* __restrict__ lng,
                                                   const float* __restrict__ lnb,
                                                   const float* __restrict__ hW,
                                                   const float* __restrict__ hb,
                                                   float* __restrict__ out) {
    int w = threadIdx.x >> 5, lane = threadIdx.x & 31;
    int row = blockIdx.x * 8 + w;
    const float4* h4 = (const float4*)(g_h0 + (size_t)row * HID);
    float4 v[16];
    float s = 0.f, ss = 0.f;
#pragma unroll
    for (int i = 0; i < 16; i++) {
        v[i] = h4[i * 32 + lane];
        s += v[i].x + v[i].y + v[i].z + v[i].w;
        ss += v[i].x * v[i].x + v[i].y * v[i].y + v[i].z * v[i].z + v[i].w * v[i].w;
    }
#pragma unroll
    for (int off = 16; off; off >>= 1) {
        s += __shfl_xor_sync(0xffffffffu, s, off);
        ss += __shfl_xor_sync(0xffffffffu, ss, off);
    }
    float mu = s * (1.0f / HID);
    float var = ss * (1.0f / HID) - mu * mu;
    float rs = rsqrtf(var + 1e-5f);
    float a0 = 0.f, a1 = 0.f, a2 = 0.f, a3 = 0.f;
    const float4* g4 = (const float4*)lng;
    const float4* b4 = (const float4*)lnb;
    const float4* w4 = (const float4*)hW;
#pragma unroll 1
    for (int i = 0; i < 16; i++) {
        int k4 = i * 32 + lane;
        float4 gg = g4[k4], bb = b4[k4];
        float hn[4];
        hn[0] = (v[i].x - mu) * rs * gg.x + bb.x;
        hn[1] = (v[i].y - mu) * rs * gg.y + bb.y;
        hn[2] = (v[i].z - mu) * rs * gg.z + bb.z;
        hn[3] = (v[i].w - mu) * rs * gg.w + bb.w;
#pragma unroll
        for (int j = 0; j < 4; j++) {
            float4 wr = w4[k4 * 4 + j];
            a0 += hn[j] * wr.x;
            a1 += hn[j] * wr.y;
            a2 += hn[j] * wr.z;
            a3 += hn[j] * wr.w;
        }
    }
#pragma unroll
    for (int off = 16; off; off >>= 1) {
        a0 += __shfl_xor_sync(0xffffffffu, a0, off);
        a1 += __shfl_xor_sync(0xffffffffu, a1, off);
        a2 += __shfl_xor_sync(0xffffffffu, a2, off);
        a3 += __shfl_xor_sync(0xffffffffu, a3, off);
    }
    if (lane == 0) {
        float4 hbv = *(const float4*)hb;
        float4 o;
        o.x = a0 + hbv.x; o.y = a1 + hbv.y; o.z = a2 + hbv.z; o.w = a3 + hbv.w;
        ((float4*)out)[row] = o;
    }
}

// ============================================================
extern "C" void kernel_launch(void* const* d_in, const int* in_sizes, int n_in,
                              void* d_out, int out_size) {
    const float* x   = (const float*)d_in[0];
    const float* eW  = (const float*)d_in[1];
    const float* eb  = (const float*)d_in[2];
    const float* lW  = (const float*)d_in[3];
    const float* lb  = (const float*)d_in[4];
    const float* lng = (const float*)d_in[5];
    const float* lnb = (const float*)d_in[6];
    const float* hW  = (const float*)d_in[7];
    const float* hb  = (const float*)d_in[8];

    cudaFuncSetAttribute(gemm_kernel, cudaFuncAttributeMaxDynamicSharedMemorySize, DYNSMEM);

    patch_kernel<<<BATCH / 8, 256>>>(x);
    wtrans_kernel<<<dim3(HID / 32, HID / 32, NLAYER), dim3(32, 8)>>>(lW);
    embed_kernel<<<dim3(HID / 128, BATCH / 64), 256>>>(eW, eb);
    for (int l = 0; l < NLAYER; l++)
        gemm_kernel<<<dim3(HID / NT, BATCH / MT), NTHR, DYNSMEM>>>(l, l & 1, lb + (size_t)l * HID);
    head_kernel<<<BATCH / 8, 256>>>(lng, lnb, hW, hb, (float*)d_out);
}